// round 6
// baseline (speedup 1.0000x reference)
#include <cuda_runtime.h>
#include <cstdint>

// YOLO head decode: x[32, 3*85, 80, 80] fp32 -> out[32, 3*80*80, 85] fp32
//   c=0: (sigmoid(v) + grid_x) * 640^2      c=1: (sigmoid(v) + grid_y) * 640^2
//   c=2: exp(v) * anchor_w[a] * 640^2       c=3: exp(v) * anchor_h[a] * 640^2
//   c>=4: sigmoid(v)
//
// R6: persistent CTAs (148*6 = 888) with software-pipelined prefetch.
// Per loop iteration: drain prev TMA bulk store -> transform prefetched
// registers into smem -> issue bulk store -> prefetch next tile's 6 LDG.128s
// (overlapping the store drain + barrier). Removes the per-wave cold-start
// LDG latency that left issue at 28.8% / DRAM at 76% in R5.

#define NBATCH   32
#define NANCH    3
#define NCH      85                  // C+5
#define SPATIAL  6400                // 80*80
#define GW       80
#define TILE     64                  // spatial locations per tile
#define NTILES   (SPATIAL / TILE)    // 100
#define TOTTILES (NBATCH * NANCH * NTILES)   // 9600
#define THREADS  256
#define ELEMS    (TILE * NCH)        // 5440 floats
#define ELEMS4   (ELEMS / 4)         // 1360 float4
#define NBATCHJ  6                   // ceil(1360/256)
#define SCALE    409600.0f           // 640*640
#define NCTA     888                 // 148 SMs * 6 resident CTAs

__device__ __forceinline__ float fast_sigmoid(float x)
{
    float t;
    asm("tanh.approx.f32 %0, %1;" : "=f"(t) : "f"(0.5f * x));
    return fmaf(0.5f, t, 0.5f);
}

__device__ __forceinline__ void prefetch_tile(const float4* __restrict__ in4,
                                              int t, float4 v[NBATCHJ])
{
    const int na   = t / NTILES;
    const int tile = t - na * NTILES;
    const int base4 = ((na * NCH) * SPATIAL + tile * TILE) >> 2;
    #pragma unroll
    for (int j = 0; j < NBATCHJ; j++) {
        const int q = threadIdx.x + j * THREADS;
        if (q < ELEMS4) {
            const int c  = q >> 4;
            const int sq = q & 15;
            v[j] = in4[base4 + c * (SPATIAL / 4) + sq];
        }
    }
}

__global__ __launch_bounds__(THREADS)
void yolo_decode_kernel(const float* __restrict__ in, float* __restrict__ out)
{
    __shared__ __align__(128) float sm[ELEMS];   // 21.76 KB

    const float4* __restrict__ in4 = reinterpret_cast<const float4*>(in);

    int t = blockIdx.x;                 // first tile for this CTA
    float4 v[NBATCHJ];
    if (t < TOTTILES) prefetch_tile(in4, t, v);

    for (; t < TOTTILES; t += NCTA) {
        const int na   = t / NTILES;    // 0..95  (n*3 + a)
        const int tile = t - na * NTILES;
        const int a    = na % NANCH;

        const float awS = ((a == 0) ? 10.0f : (a == 1) ? 16.0f : 33.0f) * SCALE;
        const float ahS = ((a == 0) ? 13.0f : (a == 1) ? 30.0f : 23.0f) * SCALE;

        const int s_base   = tile * TILE;
        // output elem (n, a*6400+s, c): (na*6400 + s)*85 + c
        const int base_out = (na * SPATIAL + s_base) * NCH;

        // ---- drain previous iteration's bulk store before touching sm
        if (threadIdx.x == 0)
            asm volatile("cp.async.bulk.wait_group 0;" ::: "memory");
        __syncthreads();

        // ---- transform prefetched registers -> transposed smem
        #pragma unroll
        for (int j = 0; j < NBATCHJ; j++) {
            const int q = threadIdx.x + j * THREADS;
            if (q < ELEMS4) {
                const int c  = q >> 4;
                const int s0 = (q & 15) << 2;
                const float vv[4] = { v[j].x, v[j].y, v[j].z, v[j].w };
                #pragma unroll
                for (int k = 0; k < 4; k++) {
                    const float x = vv[k];
                    float r;
                    if (c >= 4) {
                        r = fast_sigmoid(x);
                    } else if (c == 0) {
                        const int sabs = s_base + s0 + k;
                        r = (fast_sigmoid(x) + (float)(sabs % GW)) * SCALE;
                    } else if (c == 1) {
                        const int sabs = s_base + s0 + k;
                        r = (fast_sigmoid(x) + (float)(sabs / GW)) * SCALE;
                    } else if (c == 2) {
                        r = __expf(x) * awS;
                    } else { // c == 3
                        r = __expf(x) * ahS;
                    }
                    sm[(s0 + k) * NCH + c] = r;
                }
            }
        }

        __syncthreads();

        // ---- issue async bulk store of the contiguous 21760-byte chunk
        if (threadIdx.x == 0) {
            uint32_t smem_addr;
            asm("{ .reg .u64 tt; cvta.to.shared.u64 tt, %1; cvt.u32.u64 %0, tt; }"
                : "=r"(smem_addr) : "l"((const void*)sm));
            asm volatile("fence.proxy.async.shared::cta;" ::: "memory");
            asm volatile(
                "cp.async.bulk.global.shared::cta.bulk_group [%0], [%1], %2;"
                :: "l"(out + base_out), "r"(smem_addr), "r"((int)(ELEMS * 4))
                : "memory");
            asm volatile("cp.async.bulk.commit_group;" ::: "memory");
        }

        // ---- prefetch next tile while the store drains (no barrier needed:
        //      v[] is private; sm isn't touched until next iteration's sync)
        const int tn = t + NCTA;
        if (tn < TOTTILES) prefetch_tile(in4, tn, v);
    }

    // final drain before CTA exit
    if (threadIdx.x == 0)
        asm volatile("cp.async.bulk.wait_group 0;" ::: "memory");
}

extern "C" void kernel_launch(void* const* d_in, const int* in_sizes, int n_in,
                              void* d_out, int out_size)
{
    const float* x   = (const float*)d_in[0];
    float*       out = (float*)d_out;
    (void)in_sizes; (void)n_in; (void)out_size;

    yolo_decode_kernel<<<NCTA, THREADS>>>(x, out);
}

// round 8
// speedup vs baseline: 1.1488x; 1.1488x over previous
#include <cuda_runtime.h>
#include <cstdint>

// YOLO head decode: x[32, 3*85, 80, 80] fp32 -> out[32, 3*80*80, 85] fp32
//   c=0: (sigmoid(v) + grid_x) * 640^2      c=1: (sigmoid(v) + grid_y) * 640^2
//   c=2: exp(v) * anchor_w[a] * 640^2       c=3: exp(v) * anchor_h[a] * 640^2
//   c>=4: sigmoid(v)
//
// R7: R5 pipeline (front-batched LDG.128 -> transform -> smem transpose ->
// one TMA bulk store), re-tiled to TILE=32 / 128 threads. 19200 CTAs,
// ~13 resident/SM (vs 6 fat ones in R5): many small staggered load bursts
// approximate steady-state DRAM demand; occ 61% -> ~81%.

#define NBATCH   32
#define NANCH    3
#define NCH      85                  // C+5
#define SPATIAL  6400                // 80*80
#define GW       80
#define TILE     32                  // spatial locations per block
#define NTILES   (SPATIAL / TILE)    // 200
#define THREADS  128
#define ELEMS    (TILE * NCH)        // 2720 floats
#define ELEMS4   (ELEMS / 4)         // 680 float4
#define NBATCHJ  6                   // ceil(680/128)
#define QPC      (TILE / 4)          // float4 per channel row = 8
#define SCALE    409600.0f           // 640*640

__device__ __forceinline__ float fast_sigmoid(float x)
{
    float t;
    asm("tanh.approx.f32 %0, %1;" : "=f"(t) : "f"(0.5f * x));
    return fmaf(0.5f, t, 0.5f);
}

__global__ __launch_bounds__(THREADS)
void yolo_decode_kernel(const float* __restrict__ in, float* __restrict__ out)
{
    __shared__ __align__(128) float sm[ELEMS];   // 10.88 KB

    const int bt   = blockIdx.x;
    const int tile = bt % NTILES;
    const int na   = bt / NTILES;      // 0..95 = n*3 + a
    const int a    = na % NANCH;

    const float awS = ((a == 0) ? 10.0f : (a == 1) ? 16.0f : 33.0f) * SCALE;
    const float ahS = ((a == 0) ? 13.0f : (a == 1) ? 30.0f : 23.0f) * SCALE;

    const int s_base   = tile * TILE;
    // input elem (n, a*85+c, s): (na*85 + c)*6400 + s
    const int base_in  = (na * NCH) * SPATIAL + s_base;
    // output elem (n, a*6400+s, c): (na*6400 + s)*85 + c
    const int base_out = (na * SPATIAL + s_base) * NCH;

    const float4* __restrict__ in4 = reinterpret_cast<const float4*>(in);
    const int base4 = base_in >> 2;    // s_base = tile*32, multiple of 4

    // ---- Phase 1a: front-batch up to 6 independent LDG.128 per thread.
    // float4 index q in [0,680): c = q/8 (channel), sq = q%8 (quad within
    // the 32-float channel row). Address: base4 + c*1600 + sq.
    float4 v[NBATCHJ];
    #pragma unroll
    for (int j = 0; j < NBATCHJ; j++) {
        const int q = threadIdx.x + j * THREADS;
        if (q < ELEMS4) {
            const int c  = q >> 3;
            const int sq = q & (QPC - 1);
            v[j] = in4[base4 + c * (SPATIAL / 4) + sq];
        }
    }

    // ---- Phase 1b: transform + transposed STS (sm[s0*85 + c]).
    #pragma unroll
    for (int j = 0; j < NBATCHJ; j++) {
        const int q = threadIdx.x + j * THREADS;
        if (q < ELEMS4) {
            const int c  = q >> 3;
            const int s0 = (q & (QPC - 1)) << 2;
            const float vv[4] = { v[j].x, v[j].y, v[j].z, v[j].w };
            #pragma unroll
            for (int k = 0; k < 4; k++) {
                const float x = vv[k];
                float r;
                if (c >= 4) {
                    r = fast_sigmoid(x);
                } else if (c == 0) {
                    const int sabs = s_base + s0 + k;
                    r = (fast_sigmoid(x) + (float)(sabs % GW)) * SCALE;
                } else if (c == 1) {
                    const int sabs = s_base + s0 + k;
                    r = (fast_sigmoid(x) + (float)(sabs / GW)) * SCALE;
                } else if (c == 2) {
                    r = __expf(x) * awS;
                } else { // c == 3
                    r = __expf(x) * ahS;
                }
                sm[(s0 + k) * NCH + c] = r;
            }
        }
    }

    __syncthreads();

    // ---- Phase 2: single TMA bulk store of the contiguous 10880-byte chunk.
    if (threadIdx.x == 0) {
        uint32_t smem_addr;
        asm("{ .reg .u64 t; cvta.to.shared.u64 t, %1; cvt.u32.u64 %0, t; }"
            : "=r"(smem_addr) : "l"((const void*)sm));
        asm volatile("fence.proxy.async.shared::cta;" ::: "memory");
        asm volatile(
            "cp.async.bulk.global.shared::cta.bulk_group [%0], [%1], %2;"
            :: "l"(out + base_out), "r"(smem_addr), "r"((int)(ELEMS * 4))
            : "memory");
        asm volatile("cp.async.bulk.commit_group;" ::: "memory");
        // Drain before CTA exit: next CTA on this SM reuses the smem slot.
        asm volatile("cp.async.bulk.wait_group 0;" ::: "memory");
    }
}

extern "C" void kernel_launch(void* const* d_in, const int* in_sizes, int n_in,
                              void* d_out, int out_size)
{
    const float* x   = (const float*)d_in[0];
    float*       out = (float*)d_out;
    (void)in_sizes; (void)n_in; (void)out_size;

    const int grid = NBATCH * NANCH * NTILES;   // 32*3*200 = 19200
    yolo_decode_kernel<<<grid, THREADS>>>(x, out);
}